// round 16
// baseline (speedup 1.0000x reference)
#include <cuda_runtime.h>
#include <cuda_fp16.h>
#include <math.h>
#include <cstdint>

#define N_NODES 50000
#define N_EDGES 800000
#define HID     64
#define NGRAPH  64
#define NC      10
#define NL      3
#define KTOT    576
#define CTOT    192

// ================= base-PTX helpers =================
__device__ __forceinline__ uint32_t smem_u32(const void* p) {
    uint32_t a;
    asm("{ .reg .u64 t; cvta.to.shared.u64 t, %1; cvt.u32.u64 %0, t; }" : "=r"(a) : "l"(p));
    return a;
}
__device__ __forceinline__ void ldm_x4(uint32_t* r, uint32_t addr) {
    asm volatile("ldmatrix.sync.aligned.m8n8.x4.shared.b16 {%0,%1,%2,%3}, [%4];"
                 : "=r"(r[0]), "=r"(r[1]), "=r"(r[2]), "=r"(r[3]) : "r"(addr));
}
__device__ __forceinline__ void mma16816(float* c, const uint32_t* a, uint32_t b0, uint32_t b1) {
    asm volatile("mma.sync.aligned.m16n8k16.row.col.f32.f16.f16.f32 "
                 "{%0,%1,%2,%3}, {%4,%5,%6,%7}, {%8,%9}, {%0,%1,%2,%3};"
                 : "+f"(c[0]), "+f"(c[1]), "+f"(c[2]), "+f"(c[3])
                 : "r"(a[0]), "r"(a[1]), "r"(a[2]), "r"(a[3]), "r"(b0), "r"(b1));
}
#define CP16(dst, src) asm volatile("cp.async.cg.shared.global [%0], [%1], 16;" :: "r"(dst), "l"(src) : "memory")
#define CP_COMMIT()    asm volatile("cp.async.commit_group;" ::: "memory")
#define CP_WAIT1()     asm volatile("cp.async.wait_group 1;" ::: "memory")

// ================= device scratch =================
__device__ float   d_x1[N_NODES * HID];
__device__ __half2 d_x1h[N_NODES * 32];     // fp16 shadow of d_x1 (gather copy)
__device__ int     d_deg[N_NODES];
__device__ int     d_rowofs[N_NODES + 1];
__device__ int     d_cursor[N_NODES];
__device__ int     d_bsum[128];
__device__ int     d_adj_src[N_EDGES];
__device__ int     d_adj_eid[N_EDGES];
__device__ __half  d_M[(size_t)N_NODES * KTOT];   // A: fp16
__device__ __half  d_WhB[(size_t)NL * CTOT * KTOT];
__device__ float   d_cc[NL * CTOT];
__device__ float   d_h[N_NODES * HID];
__device__ float   d_logdeg[N_NODES];
__device__ float   d_logsum;
__device__ float   d_bnsum[HID];
__device__ float   d_bnsq[HID];
__device__ float   d_pool[NGRAPH * HID];
__device__ int     d_pcnt[NGRAPH];

// ================= init =================
__global__ void k_zero() {
    int i = blockIdx.x * blockDim.x + threadIdx.x;
    int stride = gridDim.x * blockDim.x;
    for (int t = i; t < N_NODES; t += stride) d_deg[t] = 0;
    for (int t = i; t < NGRAPH * HID; t += stride) d_pool[t] = 0.f;
    for (int t = i; t < NGRAPH; t += stride) d_pcnt[t] = 0;
    if (i == 0) d_logsum = 0.f;
}

// ================= node encoder (writes fp32 + fp16 shadow) =================
__global__ void k_node_enc(const float* __restrict__ x,
                           const float* __restrict__ w,
                           const float* __restrict__ b) {
    __shared__ float Ws[64 * 64];
    __shared__ float xs[16][64];
    int tid = threadIdx.y * blockDim.x + threadIdx.x;
    for (int t = tid; t < 64 * 64; t += 256) Ws[t] = w[t];
    int jq = threadIdx.x, ry = threadIdx.y;
    for (int rb = blockIdx.x * 16; rb < N_NODES; rb += gridDim.x * 16) {
        __syncthreads();
        for (int t = tid; t < 16 * 64; t += 256) {
            int r = rb + t / 64;
            xs[t / 64][t % 64] = (r < N_NODES) ? x[r * 64 + (t % 64)] : 0.f;
        }
        __syncthreads();
        int row = rb + ry;
        if (row < N_NODES) {
            float a0 = b[jq * 4 + 0], a1 = b[jq * 4 + 1], a2 = b[jq * 4 + 2], a3 = b[jq * 4 + 3];
#pragma unroll
            for (int k = 0; k < 64; k++) {
                float xv = xs[ry][k];
                const float* wr = &Ws[k * 64 + jq * 4];
                a0 += xv * wr[0]; a1 += xv * wr[1]; a2 += xv * wr[2]; a3 += xv * wr[3];
            }
            float* o = &d_x1[row * 64 + jq * 4];
            o[0] = a0; o[1] = a1; o[2] = a2; o[3] = a3;
            d_x1h[row * 32 + jq * 2]     = __floats2half2_rn(a0, a1);
            d_x1h[row * 32 + jq * 2 + 1] = __floats2half2_rn(a2, a3);
        }
    }
}

// ================= degree =================
__global__ void k_deg(const int* __restrict__ ei) {
    int i = blockIdx.x * blockDim.x + threadIdx.x;
    for (int e = i; e < N_EDGES; e += gridDim.x * blockDim.x)
        atomicAdd(&d_deg[ei[N_EDGES + e]], 1);
}

// ================= scan stage A =================
__global__ void k_scanA() {
    __shared__ int s[512];
    int b = blockIdx.x, t = threadIdx.x, i = b * 512 + t;
    s[t] = (i < N_NODES) ? d_deg[i] : 0;
    __syncthreads();
    for (int off = 1; off < 512; off <<= 1) {
        int u = (t >= off) ? s[t - off] : 0;
        __syncthreads();
        s[t] += u;
        __syncthreads();
    }
    if (i < N_NODES) d_rowofs[i + 1] = s[t];
    if (t == 511) d_bsum[b] = s[511];
}

// ================= scan B+C + nodeprops + pcnt =================
__global__ void k_scanBC(const int* __restrict__ batch) {
    __shared__ int red[512];
    __shared__ float fred[512];
    int b = blockIdx.x, t = threadIdx.x;
    red[t] = (t < b) ? d_bsum[t] : 0;
    __syncthreads();
    for (int o = 256; o > 0; o >>= 1) {
        if (t < o) red[t] += red[t + o];
        __syncthreads();
    }
    int boff = red[0];
    int i = b * 512 + t;
    float lsum = 0.f;
    if (i < N_NODES) {
        int ro = d_rowofs[i + 1] + boff;
        d_rowofs[i + 1] = ro;
        int deg = d_deg[i];
        d_cursor[i] = ro - deg;
        float degf = (float)deg;
        float degc = fmaxf(degf, 1.f);
        d_logdeg[i] = logf(degc + 1.f);
        lsum = logf(degf + 1.f);
        atomicAdd(&d_pcnt[batch[i]], 1);
    }
    if (b == 0 && t == 0) d_rowofs[0] = 0;
    fred[t] = lsum;
    __syncthreads();
    for (int o = 256; o > 0; o >>= 1) {
        if (t < o) fred[t] += fred[t + o];
        __syncthreads();
    }
    if (t == 0) atomicAdd(&d_logsum, fred[0]);
}

// ================= CSR fill (split arrays) =================
__global__ void k_csr(const int* __restrict__ ei) {
    int i = blockIdx.x * blockDim.x + threadIdx.x;
    for (int e = i; e < N_EDGES; e += gridDim.x * blockDim.x) {
        int dst = ei[N_EDGES + e];
        int p = atomicAdd(&d_cursor[dst], 1);
        d_adj_src[p] = ei[e];
        d_adj_eid[p] = e;
    }
}

// ================= layer-0 fused aggregation (x fp16-gather + ea), 4x unroll =================
__global__ void k_agg_fused(const float* __restrict__ eattr,
                            const float* __restrict__ ew,
                            const float* __restrict__ eb) {
    __shared__ float Ws[16 * 64];
    __shared__ float Bs[64];
    int tid = threadIdx.x;
    for (int t = tid; t < 16 * 64; t += 256) Ws[t] = ew[t];
    if (tid < 64) Bs[tid] = eb[tid];
    if (blockIdx.x == 0 && tid < 64) { d_bnsum[tid] = 0.f; d_bnsq[tid] = 0.f; }
    __syncthreads();
    int warp = tid >> 5, lane = tid & 31;
    int n = blockIdx.x * 8 + warp;
    if (n >= N_NODES) return;
    int s0 = d_rowofs[n], s1 = d_rowofs[n + 1];
    int f0 = lane, f1 = lane + 32;
    float xs0 = 0, xs1 = 0, xq0 = 0, xq1 = 0;
    float xM0 = -3.4e38f, xM1 = -3.4e38f, xm0 = 3.4e38f, xm1 = 3.4e38f;
    float es0 = 0, es1 = 0, eq0 = 0, eq1 = 0;
    float eM0 = -3.4e38f, eM1 = -3.4e38f, em0 = 3.4e38f, em1 = 3.4e38f;
    float eb0 = Bs[f0], eb1 = Bs[f1];

    auto acc_x = [&](float2 v) {
        xs0 += v.x; xs1 += v.y;
        xq0 += v.x * v.x; xq1 += v.y * v.y;
        xM0 = fmaxf(xM0, v.x); xM1 = fmaxf(xM1, v.y);
        xm0 = fminf(xm0, v.x); xm1 = fminf(xm1, v.y);
    };
    auto acc_e = [&](float av) {
        float e0 = eb0, e1 = eb1;
#pragma unroll
        for (int kk = 0; kk < 16; kk++) {
            float a = __shfl_sync(0xffffffffu, av, kk);
            e0 += a * Ws[kk * 64 + f0];
            e1 += a * Ws[kk * 64 + f1];
        }
        es0 += e0; es1 += e1;
        eq0 += e0 * e0; eq1 += e1 * e1;
        eM0 = fmaxf(eM0, e0); eM1 = fmaxf(eM1, e1);
        em0 = fminf(em0, e0); em1 = fminf(em1, e1);
    };

    int k = s0;
    for (; k + 3 < s1; k += 4) {
        // batch adjacency loads (independent)
        int src0 = d_adj_src[k],     src1 = d_adj_src[k + 1];
        int src2 = d_adj_src[k + 2], src3 = d_adj_src[k + 3];
        int e0i = d_adj_eid[k],      e1i = d_adj_eid[k + 1];
        int e2i = d_adj_eid[k + 2],  e3i = d_adj_eid[k + 3];
        // batch gathers (independent)
        __half2 h0 = d_x1h[src0 * 32 + lane];
        __half2 h1 = d_x1h[src1 * 32 + lane];
        __half2 h2 = d_x1h[src2 * 32 + lane];
        __half2 h3 = d_x1h[src3 * 32 + lane];
        float a0 = (lane < 16) ? eattr[(size_t)e0i * 16 + lane] : 0.f;
        float a1 = (lane < 16) ? eattr[(size_t)e1i * 16 + lane] : 0.f;
        float a2 = (lane < 16) ? eattr[(size_t)e2i * 16 + lane] : 0.f;
        float a3 = (lane < 16) ? eattr[(size_t)e3i * 16 + lane] : 0.f;
        acc_x(__half22float2(h0)); acc_x(__half22float2(h1));
        acc_x(__half22float2(h2)); acc_x(__half22float2(h3));
        acc_e(a0); acc_e(a1); acc_e(a2); acc_e(a3);
    }
    for (; k < s1; k++) {
        int src0 = d_adj_src[k];
        int e0i = d_adj_eid[k];
        __half2 h0 = d_x1h[src0 * 32 + lane];
        float a0 = (lane < 16) ? eattr[(size_t)e0i * 16 + lane] : 0.f;
        acc_x(__half22float2(h0));
        acc_e(a0);
    }

    int deg = s1 - s0;
    float inv = 1.f / fmaxf((float)deg, 1.f);
    float xme0 = xs0 * inv, xme1 = xs1 * inv;
    float xst0 = sqrtf(fmaxf(xq0 * inv - xme0 * xme0, 0.f) + 1e-5f);
    float xst1 = sqrtf(fmaxf(xq1 * inv - xme1 * xme1, 0.f) + 1e-5f);
    float eme0 = es0 * inv, eme1 = es1 * inv;
    float est0 = sqrtf(fmaxf(eq0 * inv - eme0 * eme0, 0.f) + 1e-5f);
    float est1 = sqrtf(fmaxf(eq1 * inv - eme1 * eme1, 0.f) + 1e-5f);
    float2 xp;
    if (deg > 0) xp = __half22float2(d_x1h[n * 32 + lane]);
    else {
        xp = make_float2(0.f, 0.f);
        xM0 = 0; xM1 = 0; xm0 = 0; xm1 = 0;
        eM0 = 0; eM1 = 0; em0 = 0; em1 = 0;
    }
    __half2* Mr2 = (__half2*)&d_M[(size_t)n * KTOT];
    Mr2[lane]       = __floats2half2_rn(xp.x, xp.y);
    Mr2[32 + lane]  = __floats2half2_rn(xme0, xme1);
    Mr2[64 + lane]  = __floats2half2_rn(xm0, xm1);
    Mr2[96 + lane]  = __floats2half2_rn(xM0, xM1);
    Mr2[128 + lane] = __floats2half2_rn(xst0, xst1);
    __half* Mr = &d_M[(size_t)n * KTOT];
    Mr[320 + f0] = __float2half(eme0); Mr[320 + f1] = __float2half(eme1);
    Mr[384 + f0] = __float2half(em0);  Mr[384 + f1] = __float2half(em1);
    Mr[448 + f0] = __float2half(eM0);  Mr[448 + f1] = __float2half(eM1);
    Mr[512 + f0] = __float2half(est0); Mr[512 + f1] = __float2half(est1);
}

// ================= layers 1-2: x aggregation only, 4x unroll =================
__global__ void k_x_agg() {
    int tid = threadIdx.x;
    if (blockIdx.x == 0 && tid < 64) { d_bnsum[tid] = 0.f; d_bnsq[tid] = 0.f; }
    int warp = tid >> 5, lane = tid & 31;
    int n = blockIdx.x * 8 + warp;
    if (n >= N_NODES) return;
    int s0 = d_rowofs[n], s1 = d_rowofs[n + 1];
    float sm0 = 0, sm1 = 0, sq0 = 0, sq1 = 0;
    float mx0 = -3.4e38f, mx1 = -3.4e38f, mn0 = 3.4e38f, mn1 = 3.4e38f;

    auto acc_x = [&](float2 v) {
        sm0 += v.x; sm1 += v.y;
        sq0 += v.x * v.x; sq1 += v.y * v.y;
        mx0 = fmaxf(mx0, v.x); mx1 = fmaxf(mx1, v.y);
        mn0 = fminf(mn0, v.x); mn1 = fminf(mn1, v.y);
    };

    int k = s0;
    for (; k + 3 < s1; k += 4) {
        int src0 = d_adj_src[k],     src1 = d_adj_src[k + 1];
        int src2 = d_adj_src[k + 2], src3 = d_adj_src[k + 3];
        __half2 h0 = d_x1h[src0 * 32 + lane];
        __half2 h1 = d_x1h[src1 * 32 + lane];
        __half2 h2 = d_x1h[src2 * 32 + lane];
        __half2 h3 = d_x1h[src3 * 32 + lane];
        acc_x(__half22float2(h0)); acc_x(__half22float2(h1));
        acc_x(__half22float2(h2)); acc_x(__half22float2(h3));
    }
    for (; k < s1; k++) {
        __half2 h0 = d_x1h[d_adj_src[k] * 32 + lane];
        acc_x(__half22float2(h0));
    }

    int deg = s1 - s0;
    float inv = 1.f / fmaxf((float)deg, 1.f);
    float me0 = sm0 * inv, me1 = sm1 * inv;
    float st0 = sqrtf(fmaxf(sq0 * inv - me0 * me0, 0.f) + 1e-5f);
    float st1 = sqrtf(fmaxf(sq1 * inv - me1 * me1, 0.f) + 1e-5f);
    float2 xp;
    if (deg > 0) xp = __half22float2(d_x1h[n * 32 + lane]);
    else { xp = make_float2(0.f, 0.f); mx0 = 0; mx1 = 0; mn0 = 0; mn1 = 0; }
    __half2* Mr2 = (__half2*)&d_M[(size_t)n * KTOT];
    Mr2[lane]       = __floats2half2_rn(xp.x, xp.y);
    Mr2[32 + lane]  = __floats2half2_rn(me0, me1);
    Mr2[64 + lane]  = __floats2half2_rn(mn0, mn1);
    Mr2[96 + lane]  = __floats2half2_rn(mx0, mx1);
    Mr2[128 + lane] = __floats2half2_rn(st0, st1);
}

// ================= weight rearrange (fp16) + cc =================
__global__ void k_wprep(const float* __restrict__ cw) {
    int idx = blockIdx.x * blockDim.x + threadIdx.x;
    int total = NL * KTOT * CTOT;
    if (idx < total) {
        int L = idx / (KTOT * CTOT);
        int rem = idx % (KTOT * CTOT);
        int r = rem / CTOT, jp = rem % CTOT;
        int k = jp / 64, j = jp % 64;
        const float* base = cw + (size_t)L * 2304 * 64;
        float val;
        if (r < 64) {
            val = base[(k * 768 + 0 * 192 + r) * 64 + j]
                + base[(k * 768 + 1 * 192 + r) * 64 + j]
                + base[(k * 768 + 2 * 192 + r) * 64 + j];
        } else if (r < 320) {
            int s = r - 64; int agg = s >> 6, f = s & 63;
            val = base[(k * 768 + agg * 192 + 64 + f) * 64 + j];
        } else {
            int s = r - 320; int agg = s >> 6, f = s & 63;
            val = base[(k * 768 + agg * 192 + 128 + f) * 64 + j];
        }
        size_t o = ((size_t)L * CTOT + jp) * KTOT + r;
        d_WhB[o] = __float2half(val);
    }
    if (idx < NL * CTOT) {
        int L = idx / CTOT, jp = idx % CTOT, k = jp / 64, j = jp % 64;
        const float* base = cw + (size_t)L * 2304 * 64;
        float s = 0.f;
        for (int f = 0; f < 64; f++) s += base[(k * 768 + 576 + f) * 64 + j];
        d_cc[idx] = s * sqrtf(1e-5f);
    }
}

// ================= HMMA GEMM (fp16, single pass) + fused combine + BN stats =================
#define NCHUNK 18
#define STG    25600
#define SMEM_DYN (2 * STG)

__global__ void __launch_bounds__(256, 1) k_gemm_mma(int L, const float* __restrict__ convb) {
    extern __shared__ char smem[];
    __shared__ float sh_cc[192];
    __shared__ float sh_b[64];
    __shared__ float sh_s[64], sh_q[64];
    int tid = threadIdx.x, lane = tid & 31, wid = tid >> 5;
    int wm = wid >> 2, wn = wid & 3;
    uint32_t sbase = smem_u32(smem);
    const int rb = blockIdx.x * 128;
    const __half* __restrict__ WhL = d_WhB + (size_t)L * CTOT * KTOT;

    for (int t = tid; t < 192; t += 256) sh_cc[t] = d_cc[L * CTOT + t];
    if (tid < 64) { sh_b[tid] = convb[tid]; sh_s[tid] = 0.f; sh_q[tid] = 0.f; }

    auto load_stage = [&](int chunk, int slot) {
        int k0 = chunk * 32;
        uint32_t st = sbase + slot * STG;
        for (int idx = tid; idx < 512; idx += 256) {
            int r = idx >> 2, c4 = idx & 3;
            uint32_t dh = st + r * 80 + c4 * 16;
            int grow = rb + r;
            if (grow < N_NODES) {
                const char* sh = (const char*)&d_M[(size_t)grow * KTOT + k0] + c4 * 16;
                CP16(dh, sh);
            } else {
                *(float4*)(smem + (dh - sbase)) = make_float4(0.f, 0.f, 0.f, 0.f);
            }
        }
        for (int idx = tid; idx < 768; idx += 256) {
            int n = idx >> 2, c4 = idx & 3;
            uint32_t dh = st + 10240 + n * 80 + c4 * 16;
            const char* sh = (const char*)&WhL[(size_t)n * KTOT + k0] + c4 * 16;
            CP16(dh, sh);
        }
    };

    float acc[4][6][4];
#pragma unroll
    for (int i = 0; i < 4; i++)
#pragma unroll
        for (int j = 0; j < 6; j++)
#pragma unroll
            for (int q = 0; q < 4; q++) acc[i][j][q] = 0.f;

    load_stage(0, 0);
    CP_COMMIT();
    load_stage(1, 1);
    CP_COMMIT();

    int aRowSel = (lane & 15);
    int aKSel   = ((lane >> 4) & 1) * 16;
    int bRowSel = (lane & 7);
    int bTileSel = (lane >> 4) & 1;
    int bKSel   = ((lane >> 3) & 1) * 16;

    for (int c = 0; c < NCHUNK; c++) {
        CP_WAIT1();
        __syncthreads();
        uint32_t st = sbase + (c & 1) * STG;
        uint32_t aB = st, bhB = st + 10240;
#pragma unroll
        for (int ks = 0; ks < 2; ks++) {
            uint32_t ah[4][4], bh[3][4];
#pragma unroll
            for (int i = 0; i < 4; i++) {
                uint32_t addr = aB + (uint32_t)(wm * 64 + i * 16 + aRowSel) * 80 + ks * 32 + aKSel;
                ldm_x4(ah[i], addr);
            }
#pragma unroll
            for (int b = 0; b < 3; b++) {
                int g0 = b * 8 + wn * 2;
                uint32_t off = (uint32_t)((g0 + bTileSel) * 8 + bRowSel) * 80 + ks * 32 + bKSel;
                ldm_x4(bh[b], bhB + off);
            }
#pragma unroll
            for (int i = 0; i < 4; i++)
#pragma unroll
                for (int b = 0; b < 3; b++) {
                    mma16816(acc[i][b * 2 + 0], ah[i], bh[b][0], bh[b][1]);
                    mma16816(acc[i][b * 2 + 1], ah[i], bh[b][2], bh[b][3]);
                }
        }
        __syncthreads();
        if (c + 2 < NCHUNK) load_stage(c + 2, c & 1);
        CP_COMMIT();
    }

    // ---- epilogue: scaler combine + local BN partial sums ----
    float avg = d_logsum * (1.f / (float)N_NODES);
    float ls[2][2] = {{0.f, 0.f}, {0.f, 0.f}};
    float lq[2][2] = {{0.f, 0.f}, {0.f, 0.f}};
#pragma unroll
    for (int i = 0; i < 4; i++) {
        int r0 = rb + wm * 64 + i * 16 + (lane >> 2);
#pragma unroll
        for (int half = 0; half < 2; half++) {
            int row = r0 + half * 8;
            if (row < N_NODES) {
                float ld = d_logdeg[row];
                float amp = ld / avg, att = avg / ld;
#pragma unroll
                for (int jj = 0; jj < 2; jj++) {
                    int col = wn * 16 + jj * 8 + (lane & 3) * 2;
                    float c00 = acc[i][jj][half * 2 + 0],     c01 = acc[i][jj][half * 2 + 1];
                    float c10 = acc[i][2 + jj][half * 2 + 0], c11 = acc[i][2 + jj][half * 2 + 1];
                    float c20 = acc[i][4 + jj][half * 2 + 0], c21 = acc[i][4 + jj][half * 2 + 1];
                    float h0 = (c00 + sh_cc[col] + sh_b[col])
                             + amp * (c10 + sh_cc[64 + col])
                             + att * (c20 + sh_cc[128 + col]);
                    float h1 = (c01 + sh_cc[col + 1] + sh_b[col + 1])
                             + amp * (c11 + sh_cc[64 + col + 1])
                             + att * (c21 + sh_cc[128 + col + 1]);
                    *(float2*)&d_h[(size_t)row * 64 + col] = make_float2(h0, h1);
                    ls[jj][0] += h0; ls[jj][1] += h1;
                    lq[jj][0] += h0 * h0; lq[jj][1] += h1 * h1;
                }
            }
        }
    }
#pragma unroll
    for (int jj = 0; jj < 2; jj++) {
        int col = wn * 16 + jj * 8 + (lane & 3) * 2;
        atomicAdd(&sh_s[col],     ls[jj][0]);
        atomicAdd(&sh_s[col + 1], ls[jj][1]);
        atomicAdd(&sh_q[col],     lq[jj][0]);
        atomicAdd(&sh_q[col + 1], lq[jj][1]);
    }
    __syncthreads();
    if (tid < 64) {
        atomicAdd(&d_bnsum[tid], sh_s[tid]);
        atomicAdd(&d_bnsq[tid], sh_q[tid]);
    }
}

// ================= BN apply + relu + residual (+ fp16 shadow, optional pool) =================
__global__ void k_bnapply(const float* __restrict__ g, const float* __restrict__ b,
                          int do_pool, const int* __restrict__ batch) {
    int idx = blockIdx.x * blockDim.x + threadIdx.x;
    const float invN = 1.f / (float)N_NODES;
    __half* x1h = (__half*)d_x1h;
    for (int t = idx; t < N_NODES * 64; t += gridDim.x * blockDim.x) {
        int j = t & 63;
        float mu = d_bnsum[j] * invN;
        float var = d_bnsq[j] * invN - mu * mu;
        float hn = (d_h[t] - mu) * rsqrtf(var + 1e-5f) * g[j] + b[j];
        float v = d_x1[t] + fmaxf(hn, 0.f);
        d_x1[t] = v;
        x1h[t] = __float2half(v);
        if (do_pool) {
            int n = t >> 6;
            atomicAdd(&d_pool[batch[n] * 64 + j], v);
        }
    }
}

// ================= MLP head =================
__global__ void k_head(const float* __restrict__ fc1w, const float* __restrict__ fc1b,
                       const float* __restrict__ fc2w, const float* __restrict__ fc2b,
                       const float* __restrict__ fc3w, const float* __restrict__ fc3b,
                       float* __restrict__ out) {
    int g = threadIdx.x;
    if (g >= NGRAPH) return;
    float inv = 1.f / fmaxf((float)d_pcnt[g], 1.f);
    float gv[64];
    for (int k = 0; k < 64; k++) gv[k] = d_pool[g * 64 + k] * inv;
    float t1[32];
    for (int j = 0; j < 32; j++) {
        float a = fc1b[j];
        for (int k = 0; k < 64; k++) a += gv[k] * fc1w[k * 32 + j];
        t1[j] = fmaxf(a, 0.f);
    }
    float t2[16];
    for (int j = 0; j < 16; j++) {
        float a = fc2b[j];
        for (int k = 0; k < 32; k++) a += t1[k] * fc2w[k * 16 + j];
        t2[j] = fmaxf(a, 0.f);
    }
    for (int j = 0; j < 10; j++) {
        float a = fc3b[j];
        for (int k = 0; k < 16; k++) a += t2[k] * fc3w[k * 10 + j];
        out[g * 10 + j] = a;
    }
}

// ================= launch =================
extern "C" void kernel_launch(void* const* d_in, const int* in_sizes, int n_in,
                              void* d_out, int out_size) {
    const float* x     = (const float*)d_in[0];
    const int*   ei    = (const int*)d_in[1];
    const int*   batch = (const int*)d_in[2];
    const float* eattr = (const float*)d_in[3];
    const float* nodew = (const float*)d_in[4];
    const float* nodeb = (const float*)d_in[5];
    const float* edgew = (const float*)d_in[6];
    const float* edgeb = (const float*)d_in[7];
    const float* convw = (const float*)d_in[8];
    const float* convb = (const float*)d_in[9];
    const float* bng   = (const float*)d_in[10];
    const float* bnb   = (const float*)d_in[11];
    const float* fc1w  = (const float*)d_in[12];
    const float* fc1b  = (const float*)d_in[13];
    const float* fc2w  = (const float*)d_in[14];
    const float* fc2b  = (const float*)d_in[15];
    const float* fc3w  = (const float*)d_in[16];
    const float* fc3b  = (const float*)d_in[17];
    float* out = (float*)d_out;

    cudaFuncSetAttribute(k_gemm_mma, cudaFuncAttributeMaxDynamicSharedMemorySize, SMEM_DYN);

    const int NB_SCAN = (N_NODES + 511) / 512;  // 98

    k_zero<<<256, 256>>>();
    k_node_enc<<<512, dim3(16, 16)>>>(x, nodew, nodeb);
    k_deg<<<1024, 256>>>(ei);
    k_scanA<<<NB_SCAN, 512>>>();
    k_scanBC<<<NB_SCAN, 512>>>(batch);
    k_csr<<<1024, 256>>>(ei);
    k_wprep<<<(NL * KTOT * CTOT + 255) / 256, 256>>>(convw);

    const int NGEMM = (N_NODES + 127) / 128;  // 391
    const int NAGG = (N_NODES + 7) / 8;
    for (int L = 0; L < NL; L++) {
        if (L == 0) k_agg_fused<<<NAGG, 256>>>(eattr, edgew, edgeb);
        else        k_x_agg<<<NAGG, 256>>>();
        k_gemm_mma<<<NGEMM, 256, SMEM_DYN>>>(L, convb + (size_t)L * 64);
        k_bnapply<<<512, 256>>>(bng + L * 64, bnb + L * 64, (L == NL - 1) ? 1 : 0, batch);
    }

    k_head<<<1, 64>>>(fc1w, fc1b, fc2w, fc2b, fc3w, fc3b, out);
}

// round 17
// speedup vs baseline: 1.1293x; 1.1293x over previous
#include <cuda_runtime.h>
#include <cuda_fp16.h>
#include <math.h>
#include <cstdint>

#define N_NODES 50000
#define N_EDGES 800000
#define HID     64
#define NGRAPH  64
#define NC      10
#define NL      3
#define KTOT    576
#define CTOT    192

// ================= base-PTX helpers =================
__device__ __forceinline__ uint32_t smem_u32(const void* p) {
    uint32_t a;
    asm("{ .reg .u64 t; cvta.to.shared.u64 t, %1; cvt.u32.u64 %0, t; }" : "=r"(a) : "l"(p));
    return a;
}
__device__ __forceinline__ void ldm_x4(uint32_t* r, uint32_t addr) {
    asm volatile("ldmatrix.sync.aligned.m8n8.x4.shared.b16 {%0,%1,%2,%3}, [%4];"
                 : "=r"(r[0]), "=r"(r[1]), "=r"(r[2]), "=r"(r[3]) : "r"(addr));
}
__device__ __forceinline__ void mma16816(float* c, const uint32_t* a, uint32_t b0, uint32_t b1) {
    asm volatile("mma.sync.aligned.m16n8k16.row.col.f32.f16.f16.f32 "
                 "{%0,%1,%2,%3}, {%4,%5,%6,%7}, {%8,%9}, {%0,%1,%2,%3};"
                 : "+f"(c[0]), "+f"(c[1]), "+f"(c[2]), "+f"(c[3])
                 : "r"(a[0]), "r"(a[1]), "r"(a[2]), "r"(a[3]), "r"(b0), "r"(b1));
}
#define CP16(dst, src) asm volatile("cp.async.cg.shared.global [%0], [%1], 16;" :: "r"(dst), "l"(src) : "memory")
#define CP_COMMIT()    asm volatile("cp.async.commit_group;" ::: "memory")
#define CP_WAIT1()     asm volatile("cp.async.wait_group 1;" ::: "memory")

// ================= device scratch =================
__device__ float  d_x1[N_NODES * HID];
__device__ int    d_deg[N_NODES];
__device__ int    d_rowofs[N_NODES + 1];
__device__ int    d_cursor[N_NODES];
__device__ int    d_bsum[128];
__device__ int2   d_adj[N_EDGES];
__device__ __half d_M[(size_t)N_NODES * KTOT];   // A: fp16
__device__ __half d_WhB[(size_t)NL * CTOT * KTOT];
__device__ float  d_cc[NL * CTOT];
__device__ float  d_h[N_NODES * HID];
__device__ float  d_logdeg[N_NODES];
__device__ float  d_logsum;
__device__ float  d_bnsum[HID];
__device__ float  d_bnsq[HID];
__device__ float  d_pool[NGRAPH * HID];
__device__ int    d_pcnt[NGRAPH];

// ================= init =================
__global__ void k_zero() {
    int i = blockIdx.x * blockDim.x + threadIdx.x;
    int stride = gridDim.x * blockDim.x;
    for (int t = i; t < N_NODES; t += stride) d_deg[t] = 0;
    for (int t = i; t < NGRAPH * HID; t += stride) d_pool[t] = 0.f;
    for (int t = i; t < NGRAPH; t += stride) d_pcnt[t] = 0;
    if (i == 0) d_logsum = 0.f;
}

// ================= node encoder =================
__global__ void k_node_enc(const float* __restrict__ x,
                           const float* __restrict__ w,
                           const float* __restrict__ b) {
    __shared__ float Ws[64 * 64];
    __shared__ float xs[16][64];
    int tid = threadIdx.y * blockDim.x + threadIdx.x;
    for (int t = tid; t < 64 * 64; t += 256) Ws[t] = w[t];
    int jq = threadIdx.x, ry = threadIdx.y;
    for (int rb = blockIdx.x * 16; rb < N_NODES; rb += gridDim.x * 16) {
        __syncthreads();
        for (int t = tid; t < 16 * 64; t += 256) {
            int r = rb + t / 64;
            xs[t / 64][t % 64] = (r < N_NODES) ? x[r * 64 + (t % 64)] : 0.f;
        }
        __syncthreads();
        int row = rb + ry;
        if (row < N_NODES) {
            float a0 = b[jq * 4 + 0], a1 = b[jq * 4 + 1], a2 = b[jq * 4 + 2], a3 = b[jq * 4 + 3];
#pragma unroll
            for (int k = 0; k < 64; k++) {
                float xv = xs[ry][k];
                const float* wr = &Ws[k * 64 + jq * 4];
                a0 += xv * wr[0]; a1 += xv * wr[1]; a2 += xv * wr[2]; a3 += xv * wr[3];
            }
            float* o = &d_x1[row * 64 + jq * 4];
            o[0] = a0; o[1] = a1; o[2] = a2; o[3] = a3;
        }
    }
}

// ================= degree =================
__global__ void k_deg(const int* __restrict__ ei) {
    int i = blockIdx.x * blockDim.x + threadIdx.x;
    for (int e = i; e < N_EDGES; e += gridDim.x * blockDim.x)
        atomicAdd(&d_deg[ei[N_EDGES + e]], 1);
}

// ================= scan stage A =================
__global__ void k_scanA() {
    __shared__ int s[512];
    int b = blockIdx.x, t = threadIdx.x, i = b * 512 + t;
    s[t] = (i < N_NODES) ? d_deg[i] : 0;
    __syncthreads();
    for (int off = 1; off < 512; off <<= 1) {
        int u = (t >= off) ? s[t - off] : 0;
        __syncthreads();
        s[t] += u;
        __syncthreads();
    }
    if (i < N_NODES) d_rowofs[i + 1] = s[t];
    if (t == 511) d_bsum[b] = s[511];
}

// ================= scan B+C + nodeprops + pcnt =================
__global__ void k_scanBC(const int* __restrict__ batch) {
    __shared__ int red[512];
    __shared__ float fred[512];
    int b = blockIdx.x, t = threadIdx.x;
    red[t] = (t < b) ? d_bsum[t] : 0;
    __syncthreads();
    for (int o = 256; o > 0; o >>= 1) {
        if (t < o) red[t] += red[t + o];
        __syncthreads();
    }
    int boff = red[0];
    int i = b * 512 + t;
    float lsum = 0.f;
    if (i < N_NODES) {
        int ro = d_rowofs[i + 1] + boff;
        d_rowofs[i + 1] = ro;
        int deg = d_deg[i];
        d_cursor[i] = ro - deg;
        float degf = (float)deg;
        float degc = fmaxf(degf, 1.f);
        d_logdeg[i] = logf(degc + 1.f);
        lsum = logf(degf + 1.f);
        atomicAdd(&d_pcnt[batch[i]], 1);
    }
    if (b == 0 && t == 0) d_rowofs[0] = 0;
    fred[t] = lsum;
    __syncthreads();
    for (int o = 256; o > 0; o >>= 1) {
        if (t < o) fred[t] += fred[t + o];
        __syncthreads();
    }
    if (t == 0) atomicAdd(&d_logsum, fred[0]);
}

// ================= CSR fill =================
__global__ void k_csr(const int* __restrict__ ei) {
    int i = blockIdx.x * blockDim.x + threadIdx.x;
    for (int e = i; e < N_EDGES; e += gridDim.x * blockDim.x) {
        int dst = ei[N_EDGES + e];
        int p = atomicAdd(&d_cursor[dst], 1);
        d_adj[p] = make_int2(ei[e], e);
    }
}

// ================= layer-0 fused aggregation (x + ea) =================
__global__ void k_agg_fused(const float* __restrict__ eattr,
                            const float* __restrict__ ew,
                            const float* __restrict__ eb) {
    __shared__ float Ws[16 * 64];
    __shared__ float Bs[64];
    int tid = threadIdx.x;
    for (int t = tid; t < 16 * 64; t += 256) Ws[t] = ew[t];
    if (tid < 64) Bs[tid] = eb[tid];
    if (blockIdx.x == 0 && tid < 64) { d_bnsum[tid] = 0.f; d_bnsq[tid] = 0.f; }
    __syncthreads();
    int warp = tid >> 5, lane = tid & 31;
    int n = blockIdx.x * 8 + warp;
    if (n >= N_NODES) return;
    int s0 = d_rowofs[n], s1 = d_rowofs[n + 1];
    int f0 = lane, f1 = lane + 32;
    float xs0 = 0, xs1 = 0, xq0 = 0, xq1 = 0;
    float xM0 = -3.4e38f, xM1 = -3.4e38f, xm0 = 3.4e38f, xm1 = 3.4e38f;
    float es0 = 0, es1 = 0, eq0 = 0, eq1 = 0;
    float eM0 = -3.4e38f, eM1 = -3.4e38f, em0 = 3.4e38f, em1 = 3.4e38f;
    float eb0 = Bs[f0], eb1 = Bs[f1];
    int k = s0;
    for (; k + 1 < s1; k += 2) {
        int2 E0 = d_adj[k], E1 = d_adj[k + 1];
        float v00 = d_x1[E0.x * 64 + f0], v01 = d_x1[E0.x * 64 + f1];
        float v10 = d_x1[E1.x * 64 + f0], v11 = d_x1[E1.x * 64 + f1];
        float av0 = (lane < 16) ? eattr[(size_t)E0.y * 16 + lane] : 0.f;
        float av1 = (lane < 16) ? eattr[(size_t)E1.y * 16 + lane] : 0.f;
        xs0 += v00 + v10; xs1 += v01 + v11;
        xq0 += v00 * v00 + v10 * v10; xq1 += v01 * v01 + v11 * v11;
        xM0 = fmaxf(xM0, fmaxf(v00, v10)); xM1 = fmaxf(xM1, fmaxf(v01, v11));
        xm0 = fminf(xm0, fminf(v00, v10)); xm1 = fminf(xm1, fminf(v01, v11));
        float e00 = eb0, e01 = eb1, e10 = eb0, e11 = eb1;
#pragma unroll
        for (int kk = 0; kk < 16; kk++) {
            float a0 = __shfl_sync(0xffffffffu, av0, kk);
            float a1 = __shfl_sync(0xffffffffu, av1, kk);
            float w0 = Ws[kk * 64 + f0], w1 = Ws[kk * 64 + f1];
            e00 += a0 * w0; e01 += a0 * w1;
            e10 += a1 * w0; e11 += a1 * w1;
        }
        es0 += e00 + e10; es1 += e01 + e11;
        eq0 += e00 * e00 + e10 * e10; eq1 += e01 * e01 + e11 * e11;
        eM0 = fmaxf(eM0, fmaxf(e00, e10)); eM1 = fmaxf(eM1, fmaxf(e01, e11));
        em0 = fminf(em0, fminf(e00, e10)); em1 = fminf(em1, fminf(e01, e11));
    }
    if (k < s1) {
        int2 E0 = d_adj[k];
        float v00 = d_x1[E0.x * 64 + f0], v01 = d_x1[E0.x * 64 + f1];
        float av0 = (lane < 16) ? eattr[(size_t)E0.y * 16 + lane] : 0.f;
        xs0 += v00; xs1 += v01; xq0 += v00 * v00; xq1 += v01 * v01;
        xM0 = fmaxf(xM0, v00); xM1 = fmaxf(xM1, v01);
        xm0 = fminf(xm0, v00); xm1 = fminf(xm1, v01);
        float e00 = eb0, e01 = eb1;
#pragma unroll
        for (int kk = 0; kk < 16; kk++) {
            float a0 = __shfl_sync(0xffffffffu, av0, kk);
            e00 += a0 * Ws[kk * 64 + f0]; e01 += a0 * Ws[kk * 64 + f1];
        }
        es0 += e00; es1 += e01; eq0 += e00 * e00; eq1 += e01 * e01;
        eM0 = fmaxf(eM0, e00); eM1 = fmaxf(eM1, e01);
        em0 = fminf(em0, e00); em1 = fminf(em1, e01);
    }
    int deg = s1 - s0;
    float inv = 1.f / fmaxf((float)deg, 1.f);
    float xme0 = xs0 * inv, xme1 = xs1 * inv;
    float xst0 = sqrtf(fmaxf(xq0 * inv - xme0 * xme0, 0.f) + 1e-5f);
    float xst1 = sqrtf(fmaxf(xq1 * inv - xme1 * xme1, 0.f) + 1e-5f);
    float eme0 = es0 * inv, eme1 = es1 * inv;
    float est0 = sqrtf(fmaxf(eq0 * inv - eme0 * eme0, 0.f) + 1e-5f);
    float est1 = sqrtf(fmaxf(eq1 * inv - eme1 * eme1, 0.f) + 1e-5f);
    float xp0, xp1;
    if (deg > 0) { xp0 = d_x1[n * 64 + f0]; xp1 = d_x1[n * 64 + f1]; }
    else {
        xp0 = 0.f; xp1 = 0.f; xM0 = 0; xM1 = 0; xm0 = 0; xm1 = 0;
        eM0 = 0; eM1 = 0; em0 = 0; em1 = 0;
    }
    __half* Mr = &d_M[(size_t)n * KTOT];
    Mr[f0]       = __float2half(xp0);  Mr[f1]       = __float2half(xp1);
    Mr[64 + f0]  = __float2half(xme0); Mr[64 + f1]  = __float2half(xme1);
    Mr[128 + f0] = __float2half(xm0);  Mr[128 + f1] = __float2half(xm1);
    Mr[192 + f0] = __float2half(xM0);  Mr[192 + f1] = __float2half(xM1);
    Mr[256 + f0] = __float2half(xst0); Mr[256 + f1] = __float2half(xst1);
    Mr[320 + f0] = __float2half(eme0); Mr[320 + f1] = __float2half(eme1);
    Mr[384 + f0] = __float2half(em0);  Mr[384 + f1] = __float2half(em1);
    Mr[448 + f0] = __float2half(eM0);  Mr[448 + f1] = __float2half(eM1);
    Mr[512 + f0] = __float2half(est0); Mr[512 + f1] = __float2half(est1);
}

// ================= layers 1-2: x aggregation only =================
__global__ void k_x_agg() {
    int tid = threadIdx.x;
    if (blockIdx.x == 0 && tid < 64) { d_bnsum[tid] = 0.f; d_bnsq[tid] = 0.f; }
    int warp = tid >> 5, lane = tid & 31;
    int n = blockIdx.x * 8 + warp;
    if (n >= N_NODES) return;
    int s0 = d_rowofs[n], s1 = d_rowofs[n + 1];
    int f0 = lane, f1 = lane + 32;
    float sm0 = 0, sm1 = 0, sq0 = 0, sq1 = 0;
    float mx0 = -3.4e38f, mx1 = -3.4e38f, mn0 = 3.4e38f, mn1 = 3.4e38f;
    int k = s0;
    for (; k + 1 < s1; k += 2) {
        int2 E0 = d_adj[k], E1 = d_adj[k + 1];
        float v00 = d_x1[E0.x * 64 + f0], v01 = d_x1[E0.x * 64 + f1];
        float v10 = d_x1[E1.x * 64 + f0], v11 = d_x1[E1.x * 64 + f1];
        sm0 += v00 + v10; sm1 += v01 + v11;
        sq0 += v00 * v00 + v10 * v10; sq1 += v01 * v01 + v11 * v11;
        mx0 = fmaxf(mx0, fmaxf(v00, v10)); mx1 = fmaxf(mx1, fmaxf(v01, v11));
        mn0 = fminf(mn0, fminf(v00, v10)); mn1 = fminf(mn1, fminf(v01, v11));
    }
    if (k < s1) {
        int2 E0 = d_adj[k];
        float v0 = d_x1[E0.x * 64 + f0], v1 = d_x1[E0.x * 64 + f1];
        sm0 += v0; sm1 += v1; sq0 += v0 * v0; sq1 += v1 * v1;
        mx0 = fmaxf(mx0, v0); mx1 = fmaxf(mx1, v1);
        mn0 = fminf(mn0, v0); mn1 = fminf(mn1, v1);
    }
    int deg = s1 - s0;
    float inv = 1.f / fmaxf((float)deg, 1.f);
    float me0 = sm0 * inv, me1 = sm1 * inv;
    float st0 = sqrtf(fmaxf(sq0 * inv - me0 * me0, 0.f) + 1e-5f);
    float st1 = sqrtf(fmaxf(sq1 * inv - me1 * me1, 0.f) + 1e-5f);
    float xp0, xp1;
    if (deg > 0) { xp0 = d_x1[n * 64 + f0]; xp1 = d_x1[n * 64 + f1]; }
    else { xp0 = 0.f; xp1 = 0.f; mx0 = 0; mx1 = 0; mn0 = 0; mn1 = 0; }
    __half* Mr = &d_M[(size_t)n * KTOT];
    Mr[f0]       = __float2half(xp0); Mr[f1]       = __float2half(xp1);
    Mr[64 + f0]  = __float2half(me0); Mr[64 + f1]  = __float2half(me1);
    Mr[128 + f0] = __float2half(mn0); Mr[128 + f1] = __float2half(mn1);
    Mr[192 + f0] = __float2half(mx0); Mr[192 + f1] = __float2half(mx1);
    Mr[256 + f0] = __float2half(st0); Mr[256 + f1] = __float2half(st1);
}

// ================= weight rearrange (fp16) + cc =================
__global__ void k_wprep(const float* __restrict__ cw) {
    int idx = blockIdx.x * blockDim.x + threadIdx.x;
    int total = NL * KTOT * CTOT;
    if (idx < total) {
        int L = idx / (KTOT * CTOT);
        int rem = idx % (KTOT * CTOT);
        int r = rem / CTOT, jp = rem % CTOT;
        int k = jp / 64, j = jp % 64;
        const float* base = cw + (size_t)L * 2304 * 64;
        float val;
        if (r < 64) {
            val = base[(k * 768 + 0 * 192 + r) * 64 + j]
                + base[(k * 768 + 1 * 192 + r) * 64 + j]
                + base[(k * 768 + 2 * 192 + r) * 64 + j];
        } else if (r < 320) {
            int s = r - 64; int agg = s >> 6, f = s & 63;
            val = base[(k * 768 + agg * 192 + 64 + f) * 64 + j];
        } else {
            int s = r - 320; int agg = s >> 6, f = s & 63;
            val = base[(k * 768 + agg * 192 + 128 + f) * 64 + j];
        }
        size_t o = ((size_t)L * CTOT + jp) * KTOT + r;
        d_WhB[o] = __float2half(val);
    }
    if (idx < NL * CTOT) {
        int L = idx / CTOT, jp = idx % CTOT, k = jp / 64, j = jp % 64;
        const float* base = cw + (size_t)L * 2304 * 64;
        float s = 0.f;
        for (int f = 0; f < 64; f++) s += base[(k * 768 + 576 + f) * 64 + j];
        d_cc[idx] = s * sqrtf(1e-5f);
    }
}

// ================= HMMA GEMM (fp16, M=64 tile, 3 CTAs/SM) + fused combine + BN stats =================
// Stage: A[0,5120) B[5120,20480); rows stride 80B.
#define NCHUNK 18
#define STG    20480
#define SMEM_DYN (2 * STG)

__global__ void __launch_bounds__(128, 3) k_gemm_mma(int L, const float* __restrict__ convb) {
    extern __shared__ char smem[];
    __shared__ float sh_cc[192];
    __shared__ float sh_b[64];
    __shared__ float sh_s[64], sh_q[64];
    int tid = threadIdx.x, lane = tid & 31, wn = tid >> 5;  // 4 warps, wn = warp id
    uint32_t sbase = smem_u32(smem);
    const int rb = blockIdx.x * 64;
    const __half* __restrict__ WhL = d_WhB + (size_t)L * CTOT * KTOT;

    for (int t = tid; t < 192; t += 128) sh_cc[t] = d_cc[L * CTOT + t];
    if (tid < 64) { sh_b[tid] = convb[tid]; sh_s[tid] = 0.f; sh_q[tid] = 0.f; }

    auto load_stage = [&](int chunk, int slot) {
        int k0 = chunk * 32;
        uint32_t st = sbase + slot * STG;
        // A: 64 rows x 64B (32 fp16)
        for (int idx = tid; idx < 256; idx += 128) {
            int r = idx >> 2, c4 = idx & 3;
            uint32_t dh = st + r * 80 + c4 * 16;
            int grow = rb + r;
            if (grow < N_NODES) {
                const char* sh = (const char*)&d_M[(size_t)grow * KTOT + k0] + c4 * 16;
                CP16(dh, sh);
            } else {
                *(float4*)(smem + (dh - sbase)) = make_float4(0.f, 0.f, 0.f, 0.f);
            }
        }
        // B: 192 rows x 64B
        for (int idx = tid; idx < 768; idx += 128) {
            int n = idx >> 2, c4 = idx & 3;
            uint32_t dh = st + 5120 + n * 80 + c4 * 16;
            const char* sh = (const char*)&WhL[(size_t)n * KTOT + k0] + c4 * 16;
            CP16(dh, sh);
        }
    };

    float acc[4][6][4];
#pragma unroll
    for (int i = 0; i < 4; i++)
#pragma unroll
        for (int j = 0; j < 6; j++)
#pragma unroll
            for (int q = 0; q < 4; q++) acc[i][j][q] = 0.f;

    load_stage(0, 0);
    CP_COMMIT();
    load_stage(1, 1);
    CP_COMMIT();

    int aRowSel = (lane & 15);
    int aKSel   = ((lane >> 4) & 1) * 16;
    int bRowSel = (lane & 7);
    int bTileSel = (lane >> 4) & 1;
    int bKSel   = ((lane >> 3) & 1) * 16;

    for (int c = 0; c < NCHUNK; c++) {
        CP_WAIT1();
        __syncthreads();
        uint32_t st = sbase + (c & 1) * STG;
        uint32_t aB = st, bhB = st + 5120;
#pragma unroll
        for (int ks = 0; ks < 2; ks++) {
            uint32_t ah[4][4], bh[3][4];
#pragma unroll
            for (int i = 0; i < 4; i++) {
                uint32_t addr = aB + (uint32_t)(i * 16 + aRowSel) * 80 + ks * 32 + aKSel;
                ldm_x4(ah[i], addr);
            }
#pragma unroll
            for (int b = 0; b < 3; b++) {
                int g0 = b * 8 + wn * 2;
                uint32_t off = (uint32_t)((g0 + bTileSel) * 8 + bRowSel) * 80 + ks * 32 + bKSel;
                ldm_x4(bh[b], bhB + off);
            }
#pragma unroll
            for (int i = 0; i < 4; i++)
#pragma unroll
                for (int b = 0; b < 3; b++) {
                    mma16816(acc[i][b * 2 + 0], ah[i], bh[b][0], bh[b][1]);
                    mma16816(acc[i][b * 2 + 1], ah[i], bh[b][2], bh[b][3]);
                }
        }
        __syncthreads();
        if (c + 2 < NCHUNK) load_stage(c + 2, c & 1);
        CP_COMMIT();
    }

    // ---- epilogue: scaler combine + local BN partial sums ----
    float avg = d_logsum * (1.f / (float)N_NODES);
    float ls[2][2] = {{0.f, 0.f}, {0.f, 0.f}};
    float lq[2][2] = {{0.f, 0.f}, {0.f, 0.f}};
#pragma unroll
    for (int i = 0; i < 4; i++) {
        int r0 = rb + i * 16 + (lane >> 2);
#pragma unroll
        for (int half = 0; half < 2; half++) {
            int row = r0 + half * 8;
            if (row < N_NODES) {
                float ld = d_logdeg[row];
                float amp = ld / avg, att = avg / ld;
#pragma unroll
                for (int jj = 0; jj < 2; jj++) {
                    int col = wn * 16 + jj * 8 + (lane & 3) * 2;
                    float c00 = acc[i][jj][half * 2 + 0],     c01 = acc[i][jj][half * 2 + 1];
                    float c10 = acc[i][2 + jj][half * 2 + 0], c11 = acc[i][2 + jj][half * 2 + 1];
                    float c20 = acc[i][4 + jj][half * 2 + 0], c21 = acc[i][4 + jj][half * 2 + 1];
                    float h0 = (c00 + sh_cc[col] + sh_b[col])
                             + amp * (c10 + sh_cc[64 + col])
                             + att * (c20 + sh_cc[128 + col]);
                    float h1 = (c01 + sh_cc[col + 1] + sh_b[col + 1])
                             + amp * (c11 + sh_cc[64 + col + 1])
                             + att * (c21 + sh_cc[128 + col + 1]);
                    *(float2*)&d_h[(size_t)row * 64 + col] = make_float2(h0, h1);
                    ls[jj][0] += h0; ls[jj][1] += h1;
                    lq[jj][0] += h0 * h0; lq[jj][1] += h1 * h1;
                }
            }
        }
    }
#pragma unroll
    for (int jj = 0; jj < 2; jj++) {
        int col = wn * 16 + jj * 8 + (lane & 3) * 2;
        atomicAdd(&sh_s[col],     ls[jj][0]);
        atomicAdd(&sh_s[col + 1], ls[jj][1]);
        atomicAdd(&sh_q[col],     lq[jj][0]);
        atomicAdd(&sh_q[col + 1], lq[jj][1]);
    }
    __syncthreads();
    if (tid < 64) {
        atomicAdd(&d_bnsum[tid], sh_s[tid]);
        atomicAdd(&d_bnsq[tid], sh_q[tid]);
    }
}

// ================= BN apply + relu + residual (+ optional pool) =================
__global__ void k_bnapply(const float* __restrict__ g, const float* __restrict__ b,
                          int do_pool, const int* __restrict__ batch) {
    int idx = blockIdx.x * blockDim.x + threadIdx.x;
    const float invN = 1.f / (float)N_NODES;
    for (int t = idx; t < N_NODES * 64; t += gridDim.x * blockDim.x) {
        int j = t & 63;
        float mu = d_bnsum[j] * invN;
        float var = d_bnsq[j] * invN - mu * mu;
        float hn = (d_h[t] - mu) * rsqrtf(var + 1e-5f) * g[j] + b[j];
        float v = d_x1[t] + fmaxf(hn, 0.f);
        d_x1[t] = v;
        if (do_pool) {
            int n = t >> 6;
            atomicAdd(&d_pool[batch[n] * 64 + j], v);
        }
    }
}

// ================= MLP head =================
__global__ void k_head(const float* __restrict__ fc1w, const float* __restrict__ fc1b,
                       const float* __restrict__ fc2w, const float* __restrict__ fc2b,
                       const float* __restrict__ fc3w, const float* __restrict__ fc3b,
                       float* __restrict__ out) {
    int g = threadIdx.x;
    if (g >= NGRAPH) return;
    float inv = 1.f / fmaxf((float)d_pcnt[g], 1.f);
    float gv[64];
    for (int k = 0; k < 64; k++) gv[k] = d_pool[g * 64 + k] * inv;
    float t1[32];
    for (int j = 0; j < 32; j++) {
        float a = fc1b[j];
        for (int k = 0; k < 64; k++) a += gv[k] * fc1w[k * 32 + j];
        t1[j] = fmaxf(a, 0.f);
    }
    float t2[16];
    for (int j = 0; j < 16; j++) {
        float a = fc2b[j];
        for (int k = 0; k < 32; k++) a += t1[k] * fc2w[k * 16 + j];
        t2[j] = fmaxf(a, 0.f);
    }
    for (int j = 0; j < 10; j++) {
        float a = fc3b[j];
        for (int k = 0; k < 16; k++) a += t2[k] * fc3w[k * 10 + j];
        out[g * 10 + j] = a;
    }
}

// ================= launch =================
extern "C" void kernel_launch(void* const* d_in, const int* in_sizes, int n_in,
                              void* d_out, int out_size) {
    const float* x     = (const float*)d_in[0];
    const int*   ei    = (const int*)d_in[1];
    const int*   batch = (const int*)d_in[2];
    const float* eattr = (const float*)d_in[3];
    const float* nodew = (const float*)d_in[4];
    const float* nodeb = (const float*)d_in[5];
    const float* edgew = (const float*)d_in[6];
    const float* edgeb = (const float*)d_in[7];
    const float* convw = (const float*)d_in[8];
    const float* convb = (const float*)d_in[9];
    const float* bng   = (const float*)d_in[10];
    const float* bnb   = (const float*)d_in[11];
    const float* fc1w  = (const float*)d_in[12];
    const float* fc1b  = (const float*)d_in[13];
    const float* fc2w  = (const float*)d_in[14];
    const float* fc2b  = (const float*)d_in[15];
    const float* fc3w  = (const float*)d_in[16];
    const float* fc3b  = (const float*)d_in[17];
    float* out = (float*)d_out;

    cudaFuncSetAttribute(k_gemm_mma, cudaFuncAttributeMaxDynamicSharedMemorySize, SMEM_DYN);

    const int NB_SCAN = (N_NODES + 511) / 512;  // 98

    k_zero<<<256, 256>>>();
    k_node_enc<<<512, dim3(16, 16)>>>(x, nodew, nodeb);
    k_deg<<<1024, 256>>>(ei);
    k_scanA<<<NB_SCAN, 512>>>();
    k_scanBC<<<NB_SCAN, 512>>>(batch);
    k_csr<<<1024, 256>>>(ei);
    k_wprep<<<(NL * KTOT * CTOT + 255) / 256, 256>>>(convw);

    const int NGEMM = (N_NODES + 63) / 64;  // 782
    const int NAGG = (N_NODES + 7) / 8;
    for (int L = 0; L < NL; L++) {
        if (L == 0) k_agg_fused<<<NAGG, 256>>>(eattr, edgew, edgeb);
        else        k_x_agg<<<NAGG, 256>>>();
        k_gemm_mma<<<NGEMM, 128, SMEM_DYN>>>(L, convb + (size_t)L * 64);
        k_bnapply<<<512, 256>>>(bng + L * 64, bnb + L * 64, (L == NL - 1) ? 1 : 0, batch);
    }

    k_head<<<1, 64>>>(fc1w, fc1b, fc2w, fc2b, fc3w, fc3b, out);
}